// round 15
// baseline (speedup 1.0000x reference)
#include <cuda_runtime.h>
#include <cuda_fp16.h>
#include <mma.h>
#include <cstdint>
#include <stdint.h>
#include <math.h>

using namespace nvcuda;

// Problem constants
#define B_SZ   1024
#define NF_    128
#define D_     64
#define H_     8
#define MCOLS  4096
#define LN_EPS 1e-5f

// ---------------------------------------------------------------------------
// Scratch (__device__ globals)
// ---------------------------------------------------------------------------
__device__ float g_qt[(size_t)B_SZ * H_ * D_];    // [b][h][d'] folded K-query
__device__ float g_mv[(size_t)B_SZ * H_ * NF_];   // [b][h][m]  mean |V|
__device__ float g_wqt[128 * 512];                // [e][h*64+d'] folded wq/wk

// fp16 single planes
__device__ __half g_fh[2097152];                  // feature 1024x2048
__device__ __half g_hh[1048576];                  // hidden  1024x1024
__device__ __half g_wzh[8388608];                 // wz      2048x4096
__device__ __half g_whh[4194304];                 // wh      1024x4096
__device__ __half g_wvh[32768];                   // wv      64x512
__device__ __half g_Fih[8388608];                 // Fi      [b][m][d]

__device__ __forceinline__ float gelu_exact(float x) {
    return 0.5f * x * (1.0f + erff(x * 0.70710678118654752f));
}

__device__ __forceinline__ void cp_async16(uint32_t dst, const void* src) {
    asm volatile("cp.async.cg.shared.global [%0], [%1], 16;\n"
                 :: "r"(dst), "l"(__cvta_generic_to_global(src)));
}

// ---------------------------------------------------------------------------
// convert_all: single launch for all fp32 -> fp16 conversions
// ---------------------------------------------------------------------------
#define CV_F   524288
#define CV_H   (CV_F + 262144)
#define CV_WZ  (CV_H + 2097152)
#define CV_WH  (CV_WZ + 1048576)
#define CV_END (CV_WH + 8192)

__global__ __launch_bounds__(256) void convert_all_kernel(
    const float* __restrict__ feature, const float* __restrict__ hidden,
    const float* __restrict__ wz, const float* __restrict__ wh,
    const float* __restrict__ wv)
{
    const int stride = gridDim.x * blockDim.x;
    for (int j = blockIdx.x * blockDim.x + threadIdx.x; j < CV_END; j += stride) {
        const float* src; __half* dst; int off;
        if (j < CV_F)       { src = feature; dst = g_fh;  off = j; }
        else if (j < CV_H)  { src = hidden;  dst = g_hh;  off = j - CV_F; }
        else if (j < CV_WZ) { src = wz;      dst = g_wzh; off = j - CV_H; }
        else if (j < CV_WH) { src = wh;      dst = g_whh; off = j - CV_WZ; }
        else                { src = wv;      dst = g_wvh; off = j - CV_WH; }
        float4 v = ((const float4*)src)[off];
        ((__half2*)dst)[off * 2 + 0] = __halves2half2(__float2half(v.x), __float2half(v.y));
        ((__half2*)dst)[off * 2 + 1] = __halves2half2(__float2half(v.z), __float2half(v.w));
    }
}

// ---------------------------------------------------------------------------
// wqt_kernel: Wqt[e, h*64+dp] = sum_d wq[e, h*64+d] * wk[dp, h*64+d]
// ---------------------------------------------------------------------------
__global__ __launch_bounds__(256) void wqt_kernel(
    const float* __restrict__ wq,
    const float* __restrict__ wk)
{
    const int idx = blockIdx.x * 256 + threadIdx.x;
    const int e  = idx >> 9;
    const int j  = idx & 511;
    const int h  = j >> 6;
    const int dp = j & 63;
    float s = 0.f;
    const float* wqp = wq + (size_t)e * 512 + h * 64;
    const float* wkp = wk + (size_t)dp * 512 + h * 64;
    #pragma unroll 8
    for (int d = 0; d < 64; d++)
        s = fmaf(wqp[d], wkp[d], s);
    g_wqt[e * 512 + j] = s;
}

// ---------------------------------------------------------------------------
// qt_kernel: qt = command @ Wqt
// ---------------------------------------------------------------------------
#define QT_WSTR 132
#define QT_SMEM ((32 * 128 + 128 * QT_WSTR) * 4)

__global__ __launch_bounds__(256) void qt_kernel(const float* __restrict__ command)
{
    extern __shared__ float qsm[];
    float* cmds = qsm;
    float* Wq   = qsm + 32 * 128;

    const int tid = threadIdx.x;
    const int bb  = blockIdx.x * 32;
    const int jt  = blockIdx.y * 128;

    #pragma unroll
    for (int rep = 0; rep < 4; rep++) {
        const int i = tid + rep * 256;
        const int row = i >> 5, c4 = i & 31;
        float4 v = *(const float4*)(command + (size_t)(bb + row) * 128 + c4 * 4);
        *(float4*)(cmds + row * 128 + c4 * 4) = v;
    }
    #pragma unroll
    for (int rep = 0; rep < 16; rep++) {
        const int i = tid + rep * 256;
        const int row = i >> 5, c4 = i & 31;
        float4 v = *(const float4*)(g_wqt + row * 512 + jt + c4 * 4);
        *(float4*)(Wq + row * QT_WSTR + c4 * 4) = v;
    }
    __syncthreads();

    const int r = tid >> 3;
    const int g = tid & 7;
    float acc[16];
    #pragma unroll
    for (int c = 0; c < 16; c++) acc[c] = 0.f;

    #pragma unroll 4
    for (int k = 0; k < 128; k++) {
        const float a = cmds[r * 128 + k];
        const float* wp = Wq + k * QT_WSTR + g * 16;
        #pragma unroll
        for (int c = 0; c < 16; c++)
            acc[c] = fmaf(a, wp[c], acc[c]);
    }

    float* dst = g_qt + (size_t)(bb + r) * 512 + jt + g * 16;
    #pragma unroll
    for (int c4 = 0; c4 < 4; c4++)
        *(float4*)(dst + c4 * 4) = make_float4(acc[c4 * 4], acc[c4 * 4 + 1],
                                               acc[c4 * 4 + 2], acc[c4 * 4 + 3]);
}

// ---------------------------------------------------------------------------
// wmma fp16 projection GEMM + GELU + LayerNorm
//   128 threads, 4 warps (2m x 2n), warp tile 64x64; KC=64 staging
//   (half the barriers per MMA); 3-stage cp.async pipeline; fp16 Fi epilogue.
// ---------------------------------------------------------------------------
#define KC     64
#define A_STR  72
#define B_STR  136
#define C_STR  140
#define A_PLANE (128 * A_STR * 2)                 // 18432 B
#define B_PLANE (KC * B_STR * 2)                  // 17408 B
#define STAGE_B (A_PLANE + B_PLANE)               // 35840 B
#define NSTAGE 3
#define SMEM_GB 512
#define C_BYTES (128 * C_STR * 4)                 // 71680 < 3*STAGE_B
#define PROJ_SMEM (SMEM_GB + NSTAGE * STAGE_B)    // 108032 B

__global__ __launch_bounds__(128, 2) void proj_wmma_kernel(
    const float* __restrict__ gamma,
    const float* __restrict__ beta)
{
    extern __shared__ char smem[];
    const int tid = threadIdx.x;
    const int wid = tid >> 5;

    const int sel = (blockIdx.y >= 32) ? 1 : 0;
    const __half* Ah_g = sel ? g_hh  : g_fh;
    const __half* Wh_g = sel ? g_whh : g_wzh;
    const int K        = sel ? 1024  : 2048;
    const int fbase    = sel ? 64    : 0;

    const int bm = blockIdx.x * 128;
    const int bn = (blockIdx.y & 31) * 128;

    if (tid < 64) {
        *(float*)(smem + tid * 4)       = gamma[tid];
        *(float*)(smem + 256 + tid * 4) = beta[tid];
    }

    const int warp_m = wid & 1;
    const int warp_n = wid >> 1;

    wmma::fragment<wmma::accumulator, 16, 16, 16, float> acc[4][4];
    #pragma unroll
    for (int fm = 0; fm < 4; fm++)
        #pragma unroll
        for (int fn = 0; fn < 4; fn++)
            wmma::fill_fragment(acc[fm][fn], 0.0f);

    const int nK = K / KC;

    auto load_stage = [&](int it, int buf) {
        const int kt = it * KC;
        char* stg = smem + SMEM_GB + buf * STAGE_B;
        const uint32_t stg_u = (uint32_t)__cvta_generic_to_shared(stg);
        // A: 128 rows x 8 chunks(16B) = 1024; 8/thread
        #pragma unroll
        for (int rep = 0; rep < 8; rep++) {
            const int i = tid + rep * 128;
            const int r = i >> 3;
            const int c = i & 7;
            const __half* gp = Ah_g + (size_t)(bm + r) * K + kt + c * 8;
            cp_async16(stg_u + r * (A_STR * 2) + c * 16, gp);
        }
        // B: 64 k-rows x 16 chunks = 1024; 8/thread
        #pragma unroll
        for (int rep = 0; rep < 8; rep++) {
            const int i = tid + rep * 128;
            const int kk = i >> 4;
            const int c  = i & 15;
            const __half* gp = Wh_g + (size_t)(kt + kk) * MCOLS + bn + c * 8;
            cp_async16(stg_u + A_PLANE + kk * (B_STR * 2) + c * 16, gp);
        }
        asm volatile("cp.async.commit_group;");
    };

    load_stage(0, 0);
    if (nK > 1) load_stage(1, 1);

    for (int it = 0; it < nK; it++) {
        const int buf = it % NSTAGE;
        if (it + 2 < nK) {
            load_stage(it + 2, (it + 2) % NSTAGE);
            asm volatile("cp.async.wait_group 2;");
        } else if (it + 1 < nK) {
            asm volatile("cp.async.wait_group 1;");
        } else {
            asm volatile("cp.async.wait_group 0;");
        }
        __syncthreads();

        const char* stg = smem + SMEM_GB + buf * STAGE_B;
        const __half* As = (const __half*)(stg);
        const __half* Bs = (const __half*)(stg + A_PLANE);

        #pragma unroll
        for (int kk = 0; kk < KC; kk += 16) {
            wmma::fragment<wmma::matrix_a, 16, 16, 16, __half, wmma::row_major> af[4];
            #pragma unroll
            for (int fm = 0; fm < 4; fm++)
                wmma::load_matrix_sync(af[fm], As + (warp_m * 64 + fm * 16) * A_STR + kk, A_STR);
            #pragma unroll
            for (int fn = 0; fn < 4; fn++) {
                wmma::fragment<wmma::matrix_b, 16, 16, 16, __half, wmma::row_major> bf;
                wmma::load_matrix_sync(bf, Bs + kk * B_STR + warp_n * 64 + fn * 16, B_STR);
                #pragma unroll
                for (int fm = 0; fm < 4; fm++)
                    wmma::mma_sync(acc[fm][fn], af[fm], bf, acc[fm][fn]);
            }
        }
        __syncthreads();
    }

    // ---- Epilogue: GELU + LN, write fp16 Fi
    float* Cs = (float*)(smem + SMEM_GB);
    #pragma unroll
    for (int fm = 0; fm < 4; fm++)
        #pragma unroll
        for (int fn = 0; fn < 4; fn++)
            wmma::store_matrix_sync(Cs + (warp_m * 64 + fm * 16) * C_STR + warp_n * 64 + fn * 16,
                                    acc[fm][fn], C_STR, wmma::mem_row_major);
    __syncthreads();

    const float* gs = (const float*)(smem);
    const float* bs = (const float*)(smem + 256);
    #pragma unroll
    for (int r = 0; r < 2; r++) {
        const int item = tid + r * 128;
        const int row = item >> 1;
        const int grp = item & 1;
        const float* src = Cs + row * C_STR + grp * 64;

        float v[64];
        float s = 0.f, sq = 0.f;
        #pragma unroll
        for (int c = 0; c < 64; c++) {
            float x = gelu_exact(src[c]);
            v[c] = x;
            s += x; sq += x * x;
        }
        const float mu   = s * (1.f / 64.f);
        const float var  = sq * (1.f / 64.f) - mu * mu;
        const float rstd = rsqrtf(var + LN_EPS);

        const int f = fbase + (bn >> 6) + grp;
        const size_t base = ((size_t)(bm + row) * NF_ + f) * D_;
        __half2* dh = (__half2*)(g_Fih + base);
        #pragma unroll
        for (int c4 = 0; c4 < 16; c4++) {
            float ox = (v[c4 * 4 + 0] - mu) * rstd * gs[c4 * 4 + 0] + bs[c4 * 4 + 0];
            float oy = (v[c4 * 4 + 1] - mu) * rstd * gs[c4 * 4 + 1] + bs[c4 * 4 + 1];
            float oz = (v[c4 * 4 + 2] - mu) * rstd * gs[c4 * 4 + 2] + bs[c4 * 4 + 2];
            float ow = (v[c4 * 4 + 3] - mu) * rstd * gs[c4 * 4 + 3] + bs[c4 * 4 + 3];
            dh[c4 * 2 + 0] = __halves2half2(__float2half(ox), __float2half(oy));
            dh[c4 * 2 + 1] = __halves2half2(__float2half(oz), __float2half(ow));
        }
    }
}

// ---------------------------------------------------------------------------
// mv_kernel: single wv buffer -> 103KB smem -> 2 CTAs/SM. Next wv load is
// issued right after the post-MMA barrier and overlaps the Cs reduction.
// ---------------------------------------------------------------------------
#define MV_A_STR 72
#define MV_APL   (128 * MV_A_STR * 2)         // 18432
#define MV_B_STR 136
#define MV_BPL   (64 * MV_B_STR * 2)          // 17408
#define MV_C_STR 132
#define MV_SMEM  (MV_APL + MV_BPL + 128 * MV_C_STR * 4)   // 103424

__global__ __launch_bounds__(256, 2) void mv_kernel()
{
    extern __shared__ char smem[];
    const int tid = threadIdx.x;
    const int wid = tid >> 5;
    const int b   = blockIdx.x;

    char* Afi = smem;
    char* Bw  = smem + MV_APL;
    float* Cs = (float*)(Bw + MV_BPL);

    const uint32_t afi_u = (uint32_t)__cvta_generic_to_shared(Afi);
    const uint32_t bw_u  = (uint32_t)__cvta_generic_to_shared(Bw);

    // Fi load + wv chunk 0, one committed group
    {
        const size_t base = (size_t)b * NF_ * D_;
        #pragma unroll
        for (int rep = 0; rep < 4; rep++) {
            const int i = tid + rep * 256;
            const int r = i >> 3;
            const int c = i & 7;
            cp_async16(afi_u + r * (MV_A_STR * 2) + c * 16, g_Fih + base + r * 64 + c * 8);
        }
    }
    auto load_b = [&](int nc) {
        #pragma unroll
        for (int rep = 0; rep < 4; rep++) {
            const int i = tid + rep * 256;
            const int kk = i >> 4;
            const int c  = i & 15;
            cp_async16(bw_u + kk * (MV_B_STR * 2) + c * 16,
                       g_wvh + kk * 512 + nc * 128 + c * 8);
        }
        asm volatile("cp.async.commit_group;");
    };
    load_b(0);

    const int warp_m = wid & 3;
    const int warp_n = wid >> 2;

    for (int nc = 0; nc < 4; nc++) {
        asm volatile("cp.async.wait_group 0;");
        __syncthreads();

        wmma::fragment<wmma::accumulator, 16, 16, 16, float> acc[2][4];
        #pragma unroll
        for (int fm = 0; fm < 2; fm++)
            #pragma unroll
            for (int fn = 0; fn < 4; fn++)
                wmma::fill_fragment(acc[fm][fn], 0.0f);

        const __half* As = (const __half*)Afi;
        const __half* Bs = (const __half*)Bw;

        #pragma unroll
        for (int kk = 0; kk < 64; kk += 16) {
            wmma::fragment<wmma::matrix_a, 16, 16, 16, __half, wmma::row_major> af[2];
            #pragma unroll
            for (int fm = 0; fm < 2; fm++)
                wmma::load_matrix_sync(af[fm], As + (warp_m * 32 + fm * 16) * MV_A_STR + kk, MV_A_STR);
            #pragma unroll
            for (int fn = 0; fn < 4; fn++) {
                wmma::fragment<wmma::matrix_b, 16, 16, 16, __half, wmma::row_major> bf;
                wmma::load_matrix_sync(bf, Bs + kk * MV_B_STR + warp_n * 64 + fn * 16, MV_B_STR);
                #pragma unroll
                for (int fm = 0; fm < 2; fm++)
                    wmma::mma_sync(acc[fm][fn], af[fm], bf, acc[fm][fn]);
            }
        }
        __syncthreads();   // all warps done reading Bw -> safe to refill
        if (nc + 1 < 4) load_b(nc + 1);   // overlaps with Cs store + reduce

        #pragma unroll
        for (int fm = 0; fm < 2; fm++)
            #pragma unroll
            for (int fn = 0; fn < 4; fn++)
                wmma::store_matrix_sync(Cs + (warp_m * 32 + fm * 16) * MV_C_STR + warp_n * 64 + fn * 16,
                                        acc[fm][fn], MV_C_STR, wmma::mem_row_major);
        __syncthreads();

        {
            const int hh = tid >> 7;
            const int m  = tid & 127;
            const float* rowp = Cs + m * MV_C_STR + hh * 64;
            float s = 0.f;
            #pragma unroll 16
            for (int c = 0; c < 64; c++)
                s += fabsf(rowp[c]);
            g_mv[((size_t)b * 8 + nc * 2 + hh) * 128 + m] = s * (1.f / 64.f);
        }
        __syncthreads();   // Cs reuse next iteration
    }
}

// ---------------------------------------------------------------------------
// attn_lite (proven shape, fp16 Fi source): logits, softmax, gvec, S
// ---------------------------------------------------------------------------
#define FSTR 129
#define LITE_SMEM ((64 * FSTR + 512 + 1024 + 1024 + 512) * 4)

__global__ __launch_bounds__(256, 1) void attn_lite_kernel(
    const float* __restrict__ wv,
    float* __restrict__ out)
{
    extern __shared__ float sm[];
    float* Fst  = sm;
    float* qts  = Fst + 64 * FSTR;
    float* mvs  = qts + 512;
    float* Aw   = mvs + 1024;
    float* gv   = Aw + 1024;

    const int tid = threadIdx.x;
    const int b   = blockIdx.x;

    {
        const __half* Fi = g_Fih + (size_t)b * NF_ * D_;
        const int m = tid & 127, half = tid >> 7;
        #pragma unroll
        for (int v = 0; v < 4; v++) {
            const int c8 = half * 4 + v;
            const __half2* p = (const __half2*)(Fi + m * 64 + c8 * 8);
            #pragma unroll
            for (int e = 0; e < 4; e++) {
                float2 f = __half22float2(p[e]);
                Fst[(c8 * 8 + e * 2 + 0) * FSTR + m] = f.x;
                Fst[(c8 * 8 + e * 2 + 1) * FSTR + m] = f.y;
            }
        }
    }
    #pragma unroll
    for (int r = 0; r < 2; r++)
        qts[tid + r * 256] = g_qt[(size_t)b * 512 + tid + r * 256];
    #pragma unroll
    for (int r = 0; r < 4; r++)
        mvs[tid + r * 256] = g_mv[(size_t)b * 1024 + tid + r * 256];
    __syncthreads();

    #pragma unroll
    for (int r = 0; r < 4; r++) {
        const int idx = tid + r * 256;
        const int h = idx >> 7, m = idx & 127;
        float s = 0.f;
        #pragma unroll 8
        for (int k = 0; k < 64; k++)
            s = fmaf(Fst[k * FSTR + m], qts[h * 64 + k], s);
        Aw[idx] = mvs[idx] * s * 0.125f;
    }
    __syncthreads();

    {
        const int w = tid >> 5, lane = tid & 31;
        float v0 = Aw[w * 128 + lane];
        float v1 = Aw[w * 128 + lane + 32];
        float v2 = Aw[w * 128 + lane + 64];
        float v3 = Aw[w * 128 + lane + 96];
        float mx = fmaxf(fmaxf(v0, v1), fmaxf(v2, v3));
        #pragma unroll
        for (int off = 16; off >= 1; off >>= 1)
            mx = fmaxf(mx, __shfl_xor_sync(0xffffffffu, mx, off));
        v0 = expf(v0 - mx); v1 = expf(v1 - mx);
        v2 = expf(v2 - mx); v3 = expf(v3 - mx);
        float se = v0 + v1 + v2 + v3;
        #pragma unroll
        for (int off = 16; off >= 1; off >>= 1)
            se += __shfl_xor_sync(0xffffffffu, se, off);
        const float inv = 1.f / se;
        Aw[w * 128 + lane]      = v0 * inv;
        Aw[w * 128 + lane + 32] = v1 * inv;
        Aw[w * 128 + lane + 64] = v2 * inv;
        Aw[w * 128 + lane + 96] = v3 * inv;
    }
    __syncthreads();

    #pragma unroll
    for (int r = 0; r < 2; r++) {
        const int idx = tid + r * 256;
        const int h = idx >> 6, d = idx & 63;
        float s = 0.f;
        #pragma unroll 8
        for (int m = 0; m < 128; m++)
            s = fmaf(Aw[h * 128 + m], Fst[d * FSTR + m], s);
        gv[idx] = s;
    }
    __syncthreads();

    #pragma unroll
    for (int r = 0; r < 2; r++) {
        const int idx = tid + r * 256;
        const int h = idx >> 6, d = idx & 63;
        float s = 0.f;
        #pragma unroll 8
        for (int k = 0; k < 64; k++)
            s = fmaf(gv[h * 64 + k], wv[(size_t)k * 512 + h * 64 + d], s);
        out[(size_t)b * 512 + idx] = s;
    }
}

// ---------------------------------------------------------------------------
// Launch
// ---------------------------------------------------------------------------
extern "C" void kernel_launch(void* const* d_in, const int* in_sizes, int n_in,
                              void* d_out, int out_size)
{
    const float* feature  = (const float*)d_in[0];
    const float* hidden   = (const float*)d_in[1];
    const float* command  = (const float*)d_in[2];
    const float* wz       = (const float*)d_in[3];
    const float* wh       = (const float*)d_in[4];
    const float* wq       = (const float*)d_in[5];
    const float* wk       = (const float*)d_in[6];
    const float* wv       = (const float*)d_in[7];
    const float* ln_gamma = (const float*)d_in[8];
    const float* ln_beta  = (const float*)d_in[9];
    float* out = (float*)d_out;

    cudaFuncSetAttribute(proj_wmma_kernel, cudaFuncAttributeMaxDynamicSharedMemorySize, PROJ_SMEM);
    cudaFuncSetAttribute(mv_kernel, cudaFuncAttributeMaxDynamicSharedMemorySize, MV_SMEM);
    cudaFuncSetAttribute(attn_lite_kernel, cudaFuncAttributeMaxDynamicSharedMemorySize, LITE_SMEM);
    cudaFuncSetAttribute(qt_kernel, cudaFuncAttributeMaxDynamicSharedMemorySize, QT_SMEM);

    convert_all_kernel<<<2048, 256>>>(feature, hidden, wz, wh, wv);

    wqt_kernel<<<256, 256>>>(wq, wk);
    qt_kernel<<<dim3(32, 4), 256, QT_SMEM>>>(command);

    // fused projections: y 0-31 = feature@wz, y 32-63 = hidden@wh
    proj_wmma_kernel<<<dim3(8, 64), 128, PROJ_SMEM>>>(ln_gamma, ln_beta);

    mv_kernel<<<B_SZ, 256, MV_SMEM>>>();
    attn_lite_kernel<<<B_SZ, 256, LITE_SMEM>>>(wv, out);
}

// round 16
// speedup vs baseline: 1.0249x; 1.0249x over previous
#include <cuda_runtime.h>
#include <cuda_fp16.h>
#include <mma.h>
#include <cstdint>
#include <stdint.h>
#include <math.h>

using namespace nvcuda;

// Problem constants
#define B_SZ   1024
#define NF_    128
#define D_     64
#define H_     8
#define MCOLS  4096
#define LN_EPS 1e-5f

// ---------------------------------------------------------------------------
// Scratch (__device__ globals)
// ---------------------------------------------------------------------------
__device__ float g_qt[(size_t)B_SZ * H_ * D_];    // [b][h][d'] folded K-query
__device__ float g_mv[(size_t)B_SZ * H_ * NF_];   // [b][h][m]  mean |V|
__device__ float g_wqt[128 * 512];                // [e][h*64+d'] folded wq/wk

// fp16 single planes
__device__ __half g_fh[2097152];                  // feature 1024x2048
__device__ __half g_hh[1048576];                  // hidden  1024x1024
__device__ __half g_wzh[8388608];                 // wz      2048x4096
__device__ __half g_whh[4194304];                 // wh      1024x4096
__device__ __half g_wvh[32768];                   // wv      64x512
__device__ __half g_Fih[8388608];                 // Fi      [b][m][d]

__device__ __forceinline__ float gelu_exact(float x) {
    return 0.5f * x * (1.0f + erff(x * 0.70710678118654752f));
}

__device__ __forceinline__ void cp_async16(uint32_t dst, const void* src) {
    asm volatile("cp.async.cg.shared.global [%0], [%1], 16;\n"
                 :: "r"(dst), "l"(__cvta_generic_to_global(src)));
}

// ---------------------------------------------------------------------------
// convert_all: single launch for all fp32 -> fp16 conversions
// ---------------------------------------------------------------------------
#define CV_F   524288
#define CV_H   (CV_F + 262144)
#define CV_WZ  (CV_H + 2097152)
#define CV_WH  (CV_WZ + 1048576)
#define CV_END (CV_WH + 8192)

__global__ __launch_bounds__(256) void convert_all_kernel(
    const float* __restrict__ feature, const float* __restrict__ hidden,
    const float* __restrict__ wz, const float* __restrict__ wh,
    const float* __restrict__ wv)
{
    const int stride = gridDim.x * blockDim.x;
    for (int j = blockIdx.x * blockDim.x + threadIdx.x; j < CV_END; j += stride) {
        const float* src; __half* dst; int off;
        if (j < CV_F)       { src = feature; dst = g_fh;  off = j; }
        else if (j < CV_H)  { src = hidden;  dst = g_hh;  off = j - CV_F; }
        else if (j < CV_WZ) { src = wz;      dst = g_wzh; off = j - CV_H; }
        else if (j < CV_WH) { src = wh;      dst = g_whh; off = j - CV_WZ; }
        else                { src = wv;      dst = g_wvh; off = j - CV_WH; }
        float4 v = ((const float4*)src)[off];
        ((__half2*)dst)[off * 2 + 0] = __halves2half2(__float2half(v.x), __float2half(v.y));
        ((__half2*)dst)[off * 2 + 1] = __halves2half2(__float2half(v.z), __float2half(v.w));
    }
}

// ---------------------------------------------------------------------------
// wqt_kernel: Wqt[e, h*64+dp] = sum_d wq[e, h*64+d] * wk[dp, h*64+d]
// ---------------------------------------------------------------------------
__global__ __launch_bounds__(256) void wqt_kernel(
    const float* __restrict__ wq,
    const float* __restrict__ wk)
{
    const int idx = blockIdx.x * 256 + threadIdx.x;
    const int e  = idx >> 9;
    const int j  = idx & 511;
    const int h  = j >> 6;
    const int dp = j & 63;
    float s = 0.f;
    const float* wqp = wq + (size_t)e * 512 + h * 64;
    const float* wkp = wk + (size_t)dp * 512 + h * 64;
    #pragma unroll 8
    for (int d = 0; d < 64; d++)
        s = fmaf(wqp[d], wkp[d], s);
    g_wqt[e * 512 + j] = s;
}

// ---------------------------------------------------------------------------
// qt_kernel: qt = command @ Wqt
// ---------------------------------------------------------------------------
#define QT_WSTR 132
#define QT_SMEM ((32 * 128 + 128 * QT_WSTR) * 4)

__global__ __launch_bounds__(256) void qt_kernel(const float* __restrict__ command)
{
    extern __shared__ float qsm[];
    float* cmds = qsm;
    float* Wq   = qsm + 32 * 128;

    const int tid = threadIdx.x;
    const int bb  = blockIdx.x * 32;
    const int jt  = blockIdx.y * 128;

    #pragma unroll
    for (int rep = 0; rep < 4; rep++) {
        const int i = tid + rep * 256;
        const int row = i >> 5, c4 = i & 31;
        float4 v = *(const float4*)(command + (size_t)(bb + row) * 128 + c4 * 4);
        *(float4*)(cmds + row * 128 + c4 * 4) = v;
    }
    #pragma unroll
    for (int rep = 0; rep < 16; rep++) {
        const int i = tid + rep * 256;
        const int row = i >> 5, c4 = i & 31;
        float4 v = *(const float4*)(g_wqt + row * 512 + jt + c4 * 4);
        *(float4*)(Wq + row * QT_WSTR + c4 * 4) = v;
    }
    __syncthreads();

    const int r = tid >> 3;
    const int g = tid & 7;
    float acc[16];
    #pragma unroll
    for (int c = 0; c < 16; c++) acc[c] = 0.f;

    #pragma unroll 4
    for (int k = 0; k < 128; k++) {
        const float a = cmds[r * 128 + k];
        const float* wp = Wq + k * QT_WSTR + g * 16;
        #pragma unroll
        for (int c = 0; c < 16; c++)
            acc[c] = fmaf(a, wp[c], acc[c]);
    }

    float* dst = g_qt + (size_t)(bb + r) * 512 + jt + g * 16;
    #pragma unroll
    for (int c4 = 0; c4 < 4; c4++)
        *(float4*)(dst + c4 * 4) = make_float4(acc[c4 * 4], acc[c4 * 4 + 1],
                                               acc[c4 * 4 + 2], acc[c4 * 4 + 3]);
}

// ---------------------------------------------------------------------------
// wmma fp16 projection GEMM + GELU + LayerNorm
//   R14-proven shape: 128 threads, 4 warps (2m x 2n), warp tile 64x64, KC=32.
//   Pipeline deepened to 4 stages (4*18.9KB fits over the 71.7KB C-buffer).
// ---------------------------------------------------------------------------
#define KC     32
#define A_STR  40
#define B_STR  136
#define C_STR  140
#define A_PLANE (128 * A_STR * 2)                 // 10240 B
#define B_PLANE (KC * B_STR * 2)                  // 8704 B
#define STAGE_B (A_PLANE + B_PLANE)               // 18944 B
#define NSTAGE 4
#define SMEM_GB 512
#define C_BYTES (128 * C_STR * 4)                 // 71680 B < 4*STAGE_B (75776)
#define PROJ_SMEM (SMEM_GB + NSTAGE * STAGE_B)    // 76288 B

__global__ __launch_bounds__(128, 2) void proj_wmma_kernel(
    const float* __restrict__ gamma,
    const float* __restrict__ beta)
{
    extern __shared__ char smem[];
    const int tid = threadIdx.x;
    const int wid = tid >> 5;

    const int sel = (blockIdx.y >= 32) ? 1 : 0;
    const __half* Ah_g = sel ? g_hh  : g_fh;
    const __half* Wh_g = sel ? g_whh : g_wzh;
    const int K        = sel ? 1024  : 2048;
    const int fbase    = sel ? 64    : 0;

    const int bm = blockIdx.x * 128;
    const int bn = (blockIdx.y & 31) * 128;

    if (tid < 64) {
        *(float*)(smem + tid * 4)       = gamma[tid];
        *(float*)(smem + 256 + tid * 4) = beta[tid];
    }

    const int warp_m = wid & 1;
    const int warp_n = wid >> 1;

    wmma::fragment<wmma::accumulator, 16, 16, 16, float> acc[4][4];
    #pragma unroll
    for (int fm = 0; fm < 4; fm++)
        #pragma unroll
        for (int fn = 0; fn < 4; fn++)
            wmma::fill_fragment(acc[fm][fn], 0.0f);

    const int nK = K / KC;

    auto load_stage = [&](int it, int buf) {
        const int kt = it * KC;
        char* stg = smem + SMEM_GB + buf * STAGE_B;
        const uint32_t stg_u = (uint32_t)__cvta_generic_to_shared(stg);
        // A: 128 rows x 4 chunks(16B) = 512; 4/thread
        #pragma unroll
        for (int rep = 0; rep < 4; rep++) {
            const int i = tid + rep * 128;
            const int r = i >> 2;
            const int c = i & 3;
            const __half* gp = Ah_g + (size_t)(bm + r) * K + kt + c * 8;
            cp_async16(stg_u + r * (A_STR * 2) + c * 16, gp);
        }
        // B: 32 k-rows x 16 chunks = 512; 4/thread
        #pragma unroll
        for (int rep = 0; rep < 4; rep++) {
            const int i = tid + rep * 128;
            const int kk = i >> 4;
            const int c  = i & 15;
            const __half* gp = Wh_g + (size_t)(kt + kk) * MCOLS + bn + c * 8;
            cp_async16(stg_u + A_PLANE + kk * (B_STR * 2) + c * 16, gp);
        }
        asm volatile("cp.async.commit_group;");
    };

    // prologue: fill 3 stages ahead
    load_stage(0, 0);
    if (nK > 1) load_stage(1, 1);
    if (nK > 2) load_stage(2, 2);

    for (int it = 0; it < nK; it++) {
        const int buf = it % NSTAGE;
        if (it + 3 < nK) {
            load_stage(it + 3, (it + 3) % NSTAGE);
            asm volatile("cp.async.wait_group 3;");
        } else if (it + 2 < nK) {
            asm volatile("cp.async.wait_group 2;");
        } else if (it + 1 < nK) {
            asm volatile("cp.async.wait_group 1;");
        } else {
            asm volatile("cp.async.wait_group 0;");
        }
        __syncthreads();

        const char* stg = smem + SMEM_GB + buf * STAGE_B;
        const __half* As = (const __half*)(stg);
        const __half* Bs = (const __half*)(stg + A_PLANE);

        #pragma unroll
        for (int kk = 0; kk < KC; kk += 16) {
            wmma::fragment<wmma::matrix_a, 16, 16, 16, __half, wmma::row_major> af[4];
            #pragma unroll
            for (int fm = 0; fm < 4; fm++)
                wmma::load_matrix_sync(af[fm], As + (warp_m * 64 + fm * 16) * A_STR + kk, A_STR);
            #pragma unroll
            for (int fn = 0; fn < 4; fn++) {
                wmma::fragment<wmma::matrix_b, 16, 16, 16, __half, wmma::row_major> bf;
                wmma::load_matrix_sync(bf, Bs + kk * B_STR + warp_n * 64 + fn * 16, B_STR);
                #pragma unroll
                for (int fm = 0; fm < 4; fm++)
                    wmma::mma_sync(acc[fm][fn], af[fm], bf, acc[fm][fn]);
            }
        }
        __syncthreads();
    }

    // ---- Epilogue: GELU + LN, write fp16 Fi
    float* Cs = (float*)(smem + SMEM_GB);
    #pragma unroll
    for (int fm = 0; fm < 4; fm++)
        #pragma unroll
        for (int fn = 0; fn < 4; fn++)
            wmma::store_matrix_sync(Cs + (warp_m * 64 + fm * 16) * C_STR + warp_n * 64 + fn * 16,
                                    acc[fm][fn], C_STR, wmma::mem_row_major);
    __syncthreads();

    const float* gs = (const float*)(smem);
    const float* bs = (const float*)(smem + 256);
    #pragma unroll
    for (int r = 0; r < 2; r++) {
        const int item = tid + r * 128;
        const int row = item >> 1;
        const int grp = item & 1;
        const float* src = Cs + row * C_STR + grp * 64;

        float v[64];
        float s = 0.f, sq = 0.f;
        #pragma unroll
        for (int c = 0; c < 64; c++) {
            float x = gelu_exact(src[c]);
            v[c] = x;
            s += x; sq += x * x;
        }
        const float mu   = s * (1.f / 64.f);
        const float var  = sq * (1.f / 64.f) - mu * mu;
        const float rstd = rsqrtf(var + LN_EPS);

        const int f = fbase + (bn >> 6) + grp;
        const size_t base = ((size_t)(bm + row) * NF_ + f) * D_;
        __half2* dh = (__half2*)(g_Fih + base);
        #pragma unroll
        for (int c4 = 0; c4 < 16; c4++) {
            float ox = (v[c4 * 4 + 0] - mu) * rstd * gs[c4 * 4 + 0] + bs[c4 * 4 + 0];
            float oy = (v[c4 * 4 + 1] - mu) * rstd * gs[c4 * 4 + 1] + bs[c4 * 4 + 1];
            float oz = (v[c4 * 4 + 2] - mu) * rstd * gs[c4 * 4 + 2] + bs[c4 * 4 + 2];
            float ow = (v[c4 * 4 + 3] - mu) * rstd * gs[c4 * 4 + 3] + bs[c4 * 4 + 3];
            dh[c4 * 2 + 0] = __halves2half2(__float2half(ox), __float2half(oy));
            dh[c4 * 2 + 1] = __halves2half2(__float2half(oz), __float2half(ow));
        }
    }
}

// ---------------------------------------------------------------------------
// mv_kernel (R15-proven): single wv buffer, 2 CTAs/SM, load/reduce overlap.
// ---------------------------------------------------------------------------
#define MV_A_STR 72
#define MV_APL   (128 * MV_A_STR * 2)         // 18432
#define MV_B_STR 136
#define MV_BPL   (64 * MV_B_STR * 2)          // 17408
#define MV_C_STR 132
#define MV_SMEM  (MV_APL + MV_BPL + 128 * MV_C_STR * 4)   // 103424

__global__ __launch_bounds__(256, 2) void mv_kernel()
{
    extern __shared__ char smem[];
    const int tid = threadIdx.x;
    const int wid = tid >> 5;
    const int b   = blockIdx.x;

    char* Afi = smem;
    char* Bw  = smem + MV_APL;
    float* Cs = (float*)(Bw + MV_BPL);

    const uint32_t afi_u = (uint32_t)__cvta_generic_to_shared(Afi);
    const uint32_t bw_u  = (uint32_t)__cvta_generic_to_shared(Bw);

    {
        const size_t base = (size_t)b * NF_ * D_;
        #pragma unroll
        for (int rep = 0; rep < 4; rep++) {
            const int i = tid + rep * 256;
            const int r = i >> 3;
            const int c = i & 7;
            cp_async16(afi_u + r * (MV_A_STR * 2) + c * 16, g_Fih + base + r * 64 + c * 8);
        }
    }
    auto load_b = [&](int nc) {
        #pragma unroll
        for (int rep = 0; rep < 4; rep++) {
            const int i = tid + rep * 256;
            const int kk = i >> 4;
            const int c  = i & 15;
            cp_async16(bw_u + kk * (MV_B_STR * 2) + c * 16,
                       g_wvh + kk * 512 + nc * 128 + c * 8);
        }
        asm volatile("cp.async.commit_group;");
    };
    load_b(0);

    const int warp_m = wid & 3;
    const int warp_n = wid >> 2;

    for (int nc = 0; nc < 4; nc++) {
        asm volatile("cp.async.wait_group 0;");
        __syncthreads();

        wmma::fragment<wmma::accumulator, 16, 16, 16, float> acc[2][4];
        #pragma unroll
        for (int fm = 0; fm < 2; fm++)
            #pragma unroll
            for (int fn = 0; fn < 4; fn++)
                wmma::fill_fragment(acc[fm][fn], 0.0f);

        const __half* As = (const __half*)Afi;
        const __half* Bs = (const __half*)Bw;

        #pragma unroll
        for (int kk = 0; kk < 64; kk += 16) {
            wmma::fragment<wmma::matrix_a, 16, 16, 16, __half, wmma::row_major> af[2];
            #pragma unroll
            for (int fm = 0; fm < 2; fm++)
                wmma::load_matrix_sync(af[fm], As + (warp_m * 32 + fm * 16) * MV_A_STR + kk, MV_A_STR);
            #pragma unroll
            for (int fn = 0; fn < 4; fn++) {
                wmma::fragment<wmma::matrix_b, 16, 16, 16, __half, wmma::row_major> bf;
                wmma::load_matrix_sync(bf, Bs + kk * MV_B_STR + warp_n * 64 + fn * 16, MV_B_STR);
                #pragma unroll
                for (int fm = 0; fm < 2; fm++)
                    wmma::mma_sync(acc[fm][fn], af[fm], bf, acc[fm][fn]);
            }
        }
        __syncthreads();   // all warps done reading Bw -> safe to refill
        if (nc + 1 < 4) load_b(nc + 1);   // overlaps with Cs store + reduce

        #pragma unroll
        for (int fm = 0; fm < 2; fm++)
            #pragma unroll
            for (int fn = 0; fn < 4; fn++)
                wmma::store_matrix_sync(Cs + (warp_m * 32 + fm * 16) * MV_C_STR + warp_n * 64 + fn * 16,
                                        acc[fm][fn], MV_C_STR, wmma::mem_row_major);
        __syncthreads();

        {
            const int hh = tid >> 7;
            const int m  = tid & 127;
            const float* rowp = Cs + m * MV_C_STR + hh * 64;
            float s = 0.f;
            #pragma unroll 16
            for (int c = 0; c < 64; c++)
                s += fabsf(rowp[c]);
            g_mv[((size_t)b * 8 + nc * 2 + hh) * 128 + m] = s * (1.f / 64.f);
        }
        __syncthreads();   // Cs reuse next iteration
    }
}

// ---------------------------------------------------------------------------
// attn_lite (proven shape, fp16 Fi source): logits, softmax, gvec, S
// ---------------------------------------------------------------------------
#define FSTR 129
#define LITE_SMEM ((64 * FSTR + 512 + 1024 + 1024 + 512) * 4)

__global__ __launch_bounds__(256, 1) void attn_lite_kernel(
    const float* __restrict__ wv,
    float* __restrict__ out)
{
    extern __shared__ float sm[];
    float* Fst  = sm;
    float* qts  = Fst + 64 * FSTR;
    float* mvs  = qts + 512;
    float* Aw   = mvs + 1024;
    float* gv   = Aw + 1024;

    const int tid = threadIdx.x;
    const int b   = blockIdx.x;

    {
        const __half* Fi = g_Fih + (size_t)b * NF_ * D_;
        const int m = tid & 127, half = tid >> 7;
        #pragma unroll
        for (int v = 0; v < 4; v++) {
            const int c8 = half * 4 + v;
            const __half2* p = (const __half2*)(Fi + m * 64 + c8 * 8);
            #pragma unroll
            for (int e = 0; e < 4; e++) {
                float2 f = __half22float2(p[e]);
                Fst[(c8 * 8 + e * 2 + 0) * FSTR + m] = f.x;
                Fst[(c8 * 8 + e * 2 + 1) * FSTR + m] = f.y;
            }
        }
    }
    #pragma unroll
    for (int r = 0; r < 2; r++)
        qts[tid + r * 256] = g_qt[(size_t)b * 512 + tid + r * 256];
    #pragma unroll
    for (int r = 0; r < 4; r++)
        mvs[tid + r * 256] = g_mv[(size_t)b * 1024 + tid + r * 256];
    __syncthreads();

    #pragma unroll
    for (int r = 0; r < 4; r++) {
        const int idx = tid + r * 256;
        const int h = idx >> 7, m = idx & 127;
        float s = 0.f;
        #pragma unroll 8
        for (int k = 0; k < 64; k++)
            s = fmaf(Fst[k * FSTR + m], qts[h * 64 + k], s);
        Aw[idx] = mvs[idx] * s * 0.125f;
    }
    __syncthreads();

    {
        const int w = tid >> 5, lane = tid & 31;
        float v0 = Aw[w * 128 + lane];
        float v1 = Aw[w * 128 + lane + 32];
        float v2 = Aw[w * 128 + lane + 64];
        float v3 = Aw[w * 128 + lane + 96];
        float mx = fmaxf(fmaxf(v0, v1), fmaxf(v2, v3));
        #pragma unroll
        for (int off = 16; off >= 1; off >>= 1)
            mx = fmaxf(mx, __shfl_xor_sync(0xffffffffu, mx, off));
        v0 = expf(v0 - mx); v1 = expf(v1 - mx);
        v2 = expf(v2 - mx); v3 = expf(v3 - mx);
        float se = v0 + v1 + v2 + v3;
        #pragma unroll
        for (int off = 16; off >= 1; off >>= 1)
            se += __shfl_xor_sync(0xffffffffu, se, off);
        const float inv = 1.f / se;
        Aw[w * 128 + lane]      = v0 * inv;
        Aw[w * 128 + lane + 32] = v1 * inv;
        Aw[w * 128 + lane + 64] = v2 * inv;
        Aw[w * 128 + lane + 96] = v3 * inv;
    }
    __syncthreads();

    #pragma unroll
    for (int r = 0; r < 2; r++) {
        const int idx = tid + r * 256;
        const int h = idx >> 6, d = idx & 63;
        float s = 0.f;
        #pragma unroll 8
        for (int m = 0; m < 128; m++)
            s = fmaf(Aw[h * 128 + m], Fst[d * FSTR + m], s);
        gv[idx] = s;
    }
    __syncthreads();

    #pragma unroll
    for (int r = 0; r < 2; r++) {
        const int idx = tid + r * 256;
        const int h = idx >> 6, d = idx & 63;
        float s = 0.f;
        #pragma unroll 8
        for (int k = 0; k < 64; k++)
            s = fmaf(gv[h * 64 + k], wv[(size_t)k * 512 + h * 64 + d], s);
        out[(size_t)b * 512 + idx] = s;
    }
}

// ---------------------------------------------------------------------------
// Launch
// ---------------------------------------------------------------------------
extern "C" void kernel_launch(void* const* d_in, const int* in_sizes, int n_in,
                              void* d_out, int out_size)
{
    const float* feature  = (const float*)d_in[0];
    const float* hidden   = (const float*)d_in[1];
    const float* command  = (const float*)d_in[2];
    const float* wz       = (const float*)d_in[3];
    const float* wh       = (const float*)d_in[4];
    const float* wq       = (const float*)d_in[5];
    const float* wk       = (const float*)d_in[6];
    const float* wv       = (const float*)d_in[7];
    const float* ln_gamma = (const float*)d_in[8];
    const float* ln_beta  = (const float*)d_in[9];
    float* out = (float*)d_out;

    cudaFuncSetAttribute(proj_wmma_kernel, cudaFuncAttributeMaxDynamicSharedMemorySize, PROJ_SMEM);
    cudaFuncSetAttribute(mv_kernel, cudaFuncAttributeMaxDynamicSharedMemorySize, MV_SMEM);
    cudaFuncSetAttribute(attn_lite_kernel, cudaFuncAttributeMaxDynamicSharedMemorySize, LITE_SMEM);
    cudaFuncSetAttribute(qt_kernel, cudaFuncAttributeMaxDynamicSharedMemorySize, QT_SMEM);

    convert_all_kernel<<<2048, 256>>>(feature, hidden, wz, wh, wv);

    wqt_kernel<<<256, 256>>>(wq, wk);
    qt_kernel<<<dim3(32, 4), 256, QT_SMEM>>>(command);

    // fused projections: y 0-31 = feature@wz, y 32-63 = hidden@wh
    proj_wmma_kernel<<<dim3(8, 64), 128, PROJ_SMEM>>>(ln_gamma, ln_beta);

    mv_kernel<<<B_SZ, 256, MV_SMEM>>>();
    attn_lite_kernel<<<B_SZ, 256, LITE_SMEM>>>(wv, out);
}

// round 17
// speedup vs baseline: 1.0698x; 1.0437x over previous
#include <cuda_runtime.h>
#include <cuda_fp16.h>
#include <mma.h>
#include <cstdint>
#include <stdint.h>
#include <math.h>

using namespace nvcuda;

// Problem constants
#define B_SZ   1024
#define NF_    128
#define D_     64
#define H_     8
#define MCOLS  4096
#define LN_EPS 1e-5f

// ---------------------------------------------------------------------------
// Scratch (__device__ globals)
// ---------------------------------------------------------------------------
__device__ float g_qt[(size_t)B_SZ * H_ * D_];    // [b][h][d'] folded K-query
__device__ float g_mv[(size_t)B_SZ * H_ * NF_];   // [b][h][m]  mean |V|
__device__ float g_wqt[128 * 512];                // [e][h*64+d'] folded wq/wk

// fp16 single planes
__device__ __half g_fh[2097152];                  // feature 1024x2048
__device__ __half g_hh[1048576];                  // hidden  1024x1024
__device__ __half g_wzh[8388608];                 // wz      2048x4096
__device__ __half g_whh[4194304];                 // wh      1024x4096
__device__ __half g_wvh[32768];                   // wv      64x512
__device__ __half g_Fih[8388608];                 // Fi      [b][m][d]

__device__ __forceinline__ float gelu_exact(float x) {
    return 0.5f * x * (1.0f + erff(x * 0.70710678118654752f));
}

__device__ __forceinline__ void cp_async16(uint32_t dst, const void* src) {
    asm volatile("cp.async.cg.shared.global [%0], [%1], 16;\n"
                 :: "r"(dst), "l"(__cvta_generic_to_global(src)));
}

__device__ __forceinline__ void ldsm4(uint32_t& r0, uint32_t& r1, uint32_t& r2,
                                      uint32_t& r3, uint32_t addr) {
    asm volatile("ldmatrix.sync.aligned.m8n8.x4.shared.b16 {%0,%1,%2,%3}, [%4];"
                 : "=r"(r0), "=r"(r1), "=r"(r2), "=r"(r3) : "r"(addr));
}
__device__ __forceinline__ void ldsm4t(uint32_t& r0, uint32_t& r1, uint32_t& r2,
                                       uint32_t& r3, uint32_t addr) {
    asm volatile("ldmatrix.sync.aligned.m8n8.x4.trans.shared.b16 {%0,%1,%2,%3}, [%4];"
                 : "=r"(r0), "=r"(r1), "=r"(r2), "=r"(r3) : "r"(addr));
}
__device__ __forceinline__ void mma16816(float* c, uint32_t a0, uint32_t a1,
                                         uint32_t a2, uint32_t a3,
                                         uint32_t b0, uint32_t b1) {
    asm volatile("mma.sync.aligned.m16n8k16.row.col.f32.f16.f16.f32 "
                 "{%0,%1,%2,%3}, {%4,%5,%6,%7}, {%8,%9}, {%0,%1,%2,%3};"
                 : "+f"(c[0]), "+f"(c[1]), "+f"(c[2]), "+f"(c[3])
                 : "r"(a0), "r"(a1), "r"(a2), "r"(a3), "r"(b0), "r"(b1));
}

// ---------------------------------------------------------------------------
// convert_all: single launch for all fp32 -> fp16 conversions
// ---------------------------------------------------------------------------
#define CV_F   524288
#define CV_H   (CV_F + 262144)
#define CV_WZ  (CV_H + 2097152)
#define CV_WH  (CV_WZ + 1048576)
#define CV_END (CV_WH + 8192)

__global__ __launch_bounds__(256) void convert_all_kernel(
    const float* __restrict__ feature, const float* __restrict__ hidden,
    const float* __restrict__ wz, const float* __restrict__ wh,
    const float* __restrict__ wv)
{
    const int stride = gridDim.x * blockDim.x;
    for (int j = blockIdx.x * blockDim.x + threadIdx.x; j < CV_END; j += stride) {
        const float* src; __half* dst; int off;
        if (j < CV_F)       { src = feature; dst = g_fh;  off = j; }
        else if (j < CV_H)  { src = hidden;  dst = g_hh;  off = j - CV_F; }
        else if (j < CV_WZ) { src = wz;      dst = g_wzh; off = j - CV_H; }
        else if (j < CV_WH) { src = wh;      dst = g_whh; off = j - CV_WZ; }
        else                { src = wv;      dst = g_wvh; off = j - CV_WH; }
        float4 v = ((const float4*)src)[off];
        ((__half2*)dst)[off * 2 + 0] = __halves2half2(__float2half(v.x), __float2half(v.y));
        ((__half2*)dst)[off * 2 + 1] = __halves2half2(__float2half(v.z), __float2half(v.w));
    }
}

// ---------------------------------------------------------------------------
// wqt_kernel: Wqt[e, h*64+dp] = sum_d wq[e, h*64+d] * wk[dp, h*64+d]
// ---------------------------------------------------------------------------
__global__ __launch_bounds__(256) void wqt_kernel(
    const float* __restrict__ wq,
    const float* __restrict__ wk)
{
    const int idx = blockIdx.x * 256 + threadIdx.x;
    const int e  = idx >> 9;
    const int j  = idx & 511;
    const int h  = j >> 6;
    const int dp = j & 63;
    float s = 0.f;
    const float* wqp = wq + (size_t)e * 512 + h * 64;
    const float* wkp = wk + (size_t)dp * 512 + h * 64;
    #pragma unroll 8
    for (int d = 0; d < 64; d++)
        s = fmaf(wqp[d], wkp[d], s);
    g_wqt[e * 512 + j] = s;
}

// ---------------------------------------------------------------------------
// qt_kernel: qt = command @ Wqt
// ---------------------------------------------------------------------------
#define QT_WSTR 132
#define QT_SMEM ((32 * 128 + 128 * QT_WSTR) * 4)

__global__ __launch_bounds__(256) void qt_kernel(const float* __restrict__ command)
{
    extern __shared__ float qsm[];
    float* cmds = qsm;
    float* Wq   = qsm + 32 * 128;

    const int tid = threadIdx.x;
    const int bb  = blockIdx.x * 32;
    const int jt  = blockIdx.y * 128;

    #pragma unroll
    for (int rep = 0; rep < 4; rep++) {
        const int i = tid + rep * 256;
        const int row = i >> 5, c4 = i & 31;
        float4 v = *(const float4*)(command + (size_t)(bb + row) * 128 + c4 * 4);
        *(float4*)(cmds + row * 128 + c4 * 4) = v;
    }
    #pragma unroll
    for (int rep = 0; rep < 16; rep++) {
        const int i = tid + rep * 256;
        const int row = i >> 5, c4 = i & 31;
        float4 v = *(const float4*)(g_wqt + row * 512 + jt + c4 * 4);
        *(float4*)(Wq + row * QT_WSTR + c4 * 4) = v;
    }
    __syncthreads();

    const int r = tid >> 3;
    const int g = tid & 7;
    float acc[16];
    #pragma unroll
    for (int c = 0; c < 16; c++) acc[c] = 0.f;

    #pragma unroll 4
    for (int k = 0; k < 128; k++) {
        const float a = cmds[r * 128 + k];
        const float* wp = Wq + k * QT_WSTR + g * 16;
        #pragma unroll
        for (int c = 0; c < 16; c++)
            acc[c] = fmaf(a, wp[c], acc[c]);
    }

    float* dst = g_qt + (size_t)(bb + r) * 512 + jt + g * 16;
    #pragma unroll
    for (int c4 = 0; c4 < 4; c4++)
        *(float4*)(dst + c4 * 4) = make_float4(acc[c4 * 4], acc[c4 * 4 + 1],
                                               acc[c4 * 4 + 2], acc[c4 * 4 + 3]);
}

// ---------------------------------------------------------------------------
// raw mma.sync fp16 projection GEMM + GELU + LayerNorm
//   128 threads, 4 warps (2m x 2n), warp tile 64x64, KC=32, 4-stage pipeline.
//   Epilogue is fully in-register: the warp's 64-col extent == one LN group;
//   each output row lives on a 4-lane quad -> 2 xor-shuffles for the LN sums.
// ---------------------------------------------------------------------------
#define KC     32
#define A_STR  40
#define B_STR  136
#define A_PLANE (128 * A_STR * 2)                 // 10240 B
#define B_PLANE (KC * B_STR * 2)                  // 8704 B
#define STAGE_B (A_PLANE + B_PLANE)               // 18944 B
#define NSTAGE 4
#define SMEM_GB 512
#define PROJ_SMEM (SMEM_GB + NSTAGE * STAGE_B)    // 76288 B

__global__ __launch_bounds__(128, 2) void proj_mma_kernel(
    const float* __restrict__ gamma,
    const float* __restrict__ beta)
{
    extern __shared__ char smem[];
    const uint32_t sbase = (uint32_t)__cvta_generic_to_shared(smem);
    const int tid  = threadIdx.x;
    const int wid  = tid >> 5;
    const int lane = tid & 31;

    const int sel = (blockIdx.y >= 32) ? 1 : 0;
    const __half* Ah_g = sel ? g_hh  : g_fh;
    const __half* Wh_g = sel ? g_whh : g_wzh;
    const int K        = sel ? 1024  : 2048;
    const int fbase    = sel ? 64    : 0;

    const int bm = blockIdx.x * 128;
    const int bn = (blockIdx.y & 31) * 128;

    if (tid < 64) {
        *(float*)(smem + tid * 4)       = gamma[tid];
        *(float*)(smem + 256 + tid * 4) = beta[tid];
    }

    const int warp_m = wid & 1;
    const int warp_n = wid >> 1;

    float acc[4][8][4];                // [fm][fn8][4] = 128 regs
    #pragma unroll
    for (int fm = 0; fm < 4; fm++)
        #pragma unroll
        for (int fn = 0; fn < 8; fn++)
            #pragma unroll
            for (int e = 0; e < 4; e++) acc[fm][fn][e] = 0.f;

    const int nK = K / KC;

    auto load_stage = [&](int it, int buf) {
        const int kt = it * KC;
        const uint32_t stg_u = sbase + SMEM_GB + buf * STAGE_B;
        #pragma unroll
        for (int rep = 0; rep < 4; rep++) {
            const int i = tid + rep * 128;
            const int r = i >> 2;
            const int c = i & 3;
            const __half* gp = Ah_g + (size_t)(bm + r) * K + kt + c * 8;
            cp_async16(stg_u + r * (A_STR * 2) + c * 16, gp);
        }
        #pragma unroll
        for (int rep = 0; rep < 4; rep++) {
            const int i = tid + rep * 128;
            const int kk = i >> 4;
            const int c  = i & 15;
            const __half* gp = Wh_g + (size_t)(kt + kk) * MCOLS + bn + c * 8;
            cp_async16(stg_u + A_PLANE + kk * (B_STR * 2) + c * 16, gp);
        }
        asm volatile("cp.async.commit_group;");
    };

    load_stage(0, 0);
    if (nK > 1) load_stage(1, 1);
    if (nK > 2) load_stage(2, 2);

    // per-warp ldmatrix base byte-offsets (within a stage)
    const uint32_t a_off = ((warp_m * 64 + (lane & 15)) * A_STR + (lane >> 4) * 8) * 2;
    const uint32_t b_off = ((lane & 15) * B_STR + warp_n * 64 + (lane >> 4) * 8) * 2;

    for (int it = 0; it < nK; it++) {
        const int buf = it % NSTAGE;
        if (it + 3 < nK) {
            load_stage(it + 3, (it + 3) % NSTAGE);
            asm volatile("cp.async.wait_group 3;");
        } else if (it + 2 < nK) {
            asm volatile("cp.async.wait_group 2;");
        } else if (it + 1 < nK) {
            asm volatile("cp.async.wait_group 1;");
        } else {
            asm volatile("cp.async.wait_group 0;");
        }
        __syncthreads();

        const uint32_t stg_u = sbase + SMEM_GB + buf * STAGE_B;
        const uint32_t aaddr = stg_u + a_off;
        const uint32_t baddr = stg_u + A_PLANE + b_off;

        #pragma unroll
        for (int kk = 0; kk < KC; kk += 16) {
            uint32_t a[4][4];
            #pragma unroll
            for (int fm = 0; fm < 4; fm++)
                ldsm4(a[fm][0], a[fm][1], a[fm][2], a[fm][3],
                      aaddr + fm * 16 * (A_STR * 2) + kk * 2);
            #pragma unroll
            for (int fnb = 0; fnb < 4; fnb++) {
                uint32_t b0, b1, b2, b3;
                ldsm4t(b0, b1, b2, b3, baddr + kk * (B_STR * 2) + fnb * 32);
                #pragma unroll
                for (int fm = 0; fm < 4; fm++) {
                    mma16816(acc[fm][fnb * 2 + 0], a[fm][0], a[fm][1], a[fm][2], a[fm][3], b0, b1);
                    mma16816(acc[fm][fnb * 2 + 1], a[fm][0], a[fm][1], a[fm][2], a[fm][3], b2, b3);
                }
            }
        }
        __syncthreads();
    }

    // ---- In-register epilogue: GELU + LN per row quad, write fp16 Fi
    const float* gs = (const float*)(smem);
    const float* bs = (const float*)(smem + 256);
    const int f = fbase + (bn >> 6) + warp_n;
    const int quad = lane >> 2;
    const int lq   = lane & 3;

    #pragma unroll
    for (int fm = 0; fm < 4; fm++) {
        #pragma unroll
        for (int hf = 0; hf < 2; hf++) {          // hf=0: acc[0..1] row; hf=1: acc[2..3] row+8
            const int row = bm + warp_m * 64 + fm * 16 + quad + hf * 8;
            float v[16];
            float s = 0.f, sq = 0.f;
            #pragma unroll
            for (int fn = 0; fn < 8; fn++) {
                float x0 = gelu_exact(acc[fm][fn][hf * 2 + 0]);
                float x1 = gelu_exact(acc[fm][fn][hf * 2 + 1]);
                v[fn * 2 + 0] = x0;
                v[fn * 2 + 1] = x1;
                s += x0 + x1; sq += x0 * x0 + x1 * x1;
            }
            s  += __shfl_xor_sync(0xffffffffu, s, 1);
            sq += __shfl_xor_sync(0xffffffffu, sq, 1);
            s  += __shfl_xor_sync(0xffffffffu, s, 2);
            sq += __shfl_xor_sync(0xffffffffu, sq, 2);
            const float mu   = s * (1.f / 64.f);
            const float var  = sq * (1.f / 64.f) - mu * mu;
            const float rstd = rsqrtf(var + LN_EPS);

            __half2* dh = (__half2*)(g_Fih + ((size_t)row * NF_ + f) * D_);
            #pragma unroll
            for (int fn = 0; fn < 8; fn++) {
                const int c0 = fn * 8 + lq * 2;
                float ox = (v[fn * 2 + 0] - mu) * rstd * gs[c0]     + bs[c0];
                float oy = (v[fn * 2 + 1] - mu) * rstd * gs[c0 + 1] + bs[c0 + 1];
                dh[c0 >> 1] = __halves2half2(__float2half(ox), __float2half(oy));
            }
        }
    }
}

// ---------------------------------------------------------------------------
// mv_kernel (R15/16-proven): single wv buffer, 2 CTAs/SM, load/reduce overlap.
// ---------------------------------------------------------------------------
#define MV_A_STR 72
#define MV_APL   (128 * MV_A_STR * 2)
#define MV_B_STR 136
#define MV_BPL   (64 * MV_B_STR * 2)
#define MV_C_STR 132
#define MV_SMEM  (MV_APL + MV_BPL + 128 * MV_C_STR * 4)

__global__ __launch_bounds__(256, 2) void mv_kernel()
{
    extern __shared__ char smem[];
    const int tid = threadIdx.x;
    const int wid = tid >> 5;
    const int b   = blockIdx.x;

    char* Afi = smem;
    char* Bw  = smem + MV_APL;
    float* Cs = (float*)(Bw + MV_BPL);

    const uint32_t afi_u = (uint32_t)__cvta_generic_to_shared(Afi);
    const uint32_t bw_u  = (uint32_t)__cvta_generic_to_shared(Bw);

    {
        const size_t base = (size_t)b * NF_ * D_;
        #pragma unroll
        for (int rep = 0; rep < 4; rep++) {
            const int i = tid + rep * 256;
            const int r = i >> 3;
            const int c = i & 7;
            cp_async16(afi_u + r * (MV_A_STR * 2) + c * 16, g_Fih + base + r * 64 + c * 8);
        }
    }
    auto load_b = [&](int nc) {
        #pragma unroll
        for (int rep = 0; rep < 4; rep++) {
            const int i = tid + rep * 256;
            const int kk = i >> 4;
            const int c  = i & 15;
            cp_async16(bw_u + kk * (MV_B_STR * 2) + c * 16,
                       g_wvh + kk * 512 + nc * 128 + c * 8);
        }
        asm volatile("cp.async.commit_group;");
    };
    load_b(0);

    const int warp_m = wid & 3;
    const int warp_n = wid >> 2;

    for (int nc = 0; nc < 4; nc++) {
        asm volatile("cp.async.wait_group 0;");
        __syncthreads();

        wmma::fragment<wmma::accumulator, 16, 16, 16, float> acc[2][4];
        #pragma unroll
        for (int fm = 0; fm < 2; fm++)
            #pragma unroll
            for (int fn = 0; fn < 4; fn++)
                wmma::fill_fragment(acc[fm][fn], 0.0f);

        const __half* As = (const __half*)Afi;
        const __half* Bs = (const __half*)Bw;

        #pragma unroll
        for (int kk = 0; kk < 64; kk += 16) {
            wmma::fragment<wmma::matrix_a, 16, 16, 16, __half, wmma::row_major> af[2];
            #pragma unroll
            for (int fm = 0; fm < 2; fm++)
                wmma::load_matrix_sync(af[fm], As + (warp_m * 32 + fm * 16) * MV_A_STR + kk, MV_A_STR);
            #pragma unroll
            for (int fn = 0; fn < 4; fn++) {
                wmma::fragment<wmma::matrix_b, 16, 16, 16, __half, wmma::row_major> bf;
                wmma::load_matrix_sync(bf, Bs + kk * MV_B_STR + warp_n * 64 + fn * 16, MV_B_STR);
                #pragma unroll
                for (int fm = 0; fm < 2; fm++)
                    wmma::mma_sync(acc[fm][fn], af[fm], bf, acc[fm][fn]);
            }
        }
        __syncthreads();
        if (nc + 1 < 4) load_b(nc + 1);

        #pragma unroll
        for (int fm = 0; fm < 2; fm++)
            #pragma unroll
            for (int fn = 0; fn < 4; fn++)
                wmma::store_matrix_sync(Cs + (warp_m * 32 + fm * 16) * MV_C_STR + warp_n * 64 + fn * 16,
                                        acc[fm][fn], MV_C_STR, wmma::mem_row_major);
        __syncthreads();

        {
            const int hh = tid >> 7;
            const int m  = tid & 127;
            const float* rowp = Cs + m * MV_C_STR + hh * 64;
            float s = 0.f;
            #pragma unroll 16
            for (int c = 0; c < 64; c++)
                s += fabsf(rowp[c]);
            g_mv[((size_t)b * 8 + nc * 2 + hh) * 128 + m] = s * (1.f / 64.f);
        }
        __syncthreads();
    }
}

// ---------------------------------------------------------------------------
// attn_lite (proven shape, fp16 Fi source): logits, softmax, gvec, S
// ---------------------------------------------------------------------------
#define FSTR 129
#define LITE_SMEM ((64 * FSTR + 512 + 1024 + 1024 + 512) * 4)

__global__ __launch_bounds__(256, 1) void attn_lite_kernel(
    const float* __restrict__ wv,
    float* __restrict__ out)
{
    extern __shared__ float sm[];
    float* Fst  = sm;
    float* qts  = Fst + 64 * FSTR;
    float* mvs  = qts + 512;
    float* Aw   = mvs + 1024;
    float* gv   = Aw + 1024;

    const int tid = threadIdx.x;
    const int b   = blockIdx.x;

    {
        const __half* Fi = g_Fih + (size_t)b * NF_ * D_;
        const int m = tid & 127, half = tid >> 7;
        #pragma unroll
        for (int v = 0; v < 4; v++) {
            const int c8 = half * 4 + v;
            const __half2* p = (const __half2*)(Fi + m * 64 + c8 * 8);
            #pragma unroll
            for (int e = 0; e < 4; e++) {
                float2 f = __half22float2(p[e]);
                Fst[(c8 * 8 + e * 2 + 0) * FSTR + m] = f.x;
                Fst[(c8 * 8 + e * 2 + 1) * FSTR + m] = f.y;
            }
        }
    }
    #pragma unroll
    for (int r = 0; r < 2; r++)
        qts[tid + r * 256] = g_qt[(size_t)b * 512 + tid + r * 256];
    #pragma unroll
    for (int r = 0; r < 4; r++)
        mvs[tid + r * 256] = g_mv[(size_t)b * 1024 + tid + r * 256];
    __syncthreads();

    #pragma unroll
    for (int r = 0; r < 4; r++) {
        const int idx = tid + r * 256;
        const int h = idx >> 7, m = idx & 127;
        float s = 0.f;
        #pragma unroll 8
        for (int k = 0; k < 64; k++)
            s = fmaf(Fst[k * FSTR + m], qts[h * 64 + k], s);
        Aw[idx] = mvs[idx] * s * 0.125f;
    }
    __syncthreads();

    {
        const int w = tid >> 5, lane = tid & 31;
        float v0 = Aw[w * 128 + lane];
        float v1 = Aw[w * 128 + lane + 32];
        float v2 = Aw[w * 128 + lane + 64];
        float v3 = Aw[w * 128 + lane + 96];
        float mx = fmaxf(fmaxf(v0, v1), fmaxf(v2, v3));
        #pragma unroll
        for (int off = 16; off >= 1; off >>= 1)
            mx = fmaxf(mx, __shfl_xor_sync(0xffffffffu, mx, off));
        v0 = expf(v0 - mx); v1 = expf(v1 - mx);
        v2 = expf(v2 - mx); v3 = expf(v3 - mx);
        float se = v0 + v1 + v2 + v3;
        #pragma unroll
        for (int off = 16; off >= 1; off >>= 1)
            se += __shfl_xor_sync(0xffffffffu, se, off);
        const float inv = 1.f / se;
        Aw[w * 128 + lane]      = v0 * inv;
        Aw[w * 128 + lane + 32] = v1 * inv;
        Aw[w * 128 + lane + 64] = v2 * inv;
        Aw[w * 128 + lane + 96] = v3 * inv;
    }
    __syncthreads();

    #pragma unroll
    for (int r = 0; r < 2; r++) {
        const int idx = tid + r * 256;
        const int h = idx >> 6, d = idx & 63;
        float s = 0.f;
        #pragma unroll 8
        for (int m = 0; m < 128; m++)
            s = fmaf(Aw[h * 128 + m], Fst[d * FSTR + m], s);
        gv[idx] = s;
    }
    __syncthreads();

    #pragma unroll
    for (int r = 0; r < 2; r++) {
        const int idx = tid + r * 256;
        const int h = idx >> 6, d = idx & 63;
        float s = 0.f;
        #pragma unroll 8
        for (int k = 0; k < 64; k++)
            s = fmaf(gv[h * 64 + k], wv[(size_t)k * 512 + h * 64 + d], s);
        out[(size_t)b * 512 + idx] = s;
    }
}

// ---------------------------------------------------------------------------
// Launch
// ---------------------------------------------------------------------------
extern "C" void kernel_launch(void* const* d_in, const int* in_sizes, int n_in,
                              void* d_out, int out_size)
{
    const float* feature  = (const float*)d_in[0];
    const float* hidden   = (const float*)d_in[1];
    const float* command  = (const float*)d_in[2];
    const float* wz       = (const float*)d_in[3];
    const float* wh       = (const float*)d_in[4];
    const float* wq       = (const float*)d_in[5];
    const float* wk       = (const float*)d_in[6];
    const float* wv       = (const float*)d_in[7];
    const float* ln_gamma = (const float*)d_in[8];
    const float* ln_beta  = (const float*)d_in[9];
    float* out = (float*)d_out;

    cudaFuncSetAttribute(proj_mma_kernel, cudaFuncAttributeMaxDynamicSharedMemorySize, PROJ_SMEM);
    cudaFuncSetAttribute(mv_kernel, cudaFuncAttributeMaxDynamicSharedMemorySize, MV_SMEM);
    cudaFuncSetAttribute(attn_lite_kernel, cudaFuncAttributeMaxDynamicSharedMemorySize, LITE_SMEM);
    cudaFuncSetAttribute(qt_kernel, cudaFuncAttributeMaxDynamicSharedMemorySize, QT_SMEM);

    convert_all_kernel<<<2048, 256>>>(feature, hidden, wz, wh, wv);

    wqt_kernel<<<256, 256>>>(wq, wk);
    qt_kernel<<<dim3(32, 4), 256, QT_SMEM>>>(command);

    // fused projections: y 0-31 = feature@wz, y 32-63 = hidden@wh
    proj_mma_kernel<<<dim3(8, 64), 128, PROJ_SMEM>>>(ln_gamma, ln_beta);

    mv_kernel<<<B_SZ, 256, MV_SMEM>>>();
    attn_lite_kernel<<<B_SZ, 256, LITE_SMEM>>>(wv, out);
}